// round 9
// baseline (speedup 1.0000x reference)
#include <cuda_runtime.h>
#include <cstdint>

// Problem constants
#define Bn  16
#define Cn  32
#define Nn  128
#define Tn  12
#define COn 64
#define NT  (Nn * Tn)            // 1536 floats per (b,i,j) row of A
#define NT4 (NT / 4)             // 384
#define NSLICE (Bn * Cn)         // 512

// prop: 32 quads x 4 CTAs. CTA cq of quad q owns k-chunk [32cq, 32cq+32)
// of slices q*16 .. q*16+15. Whole chunk (128 j x 32 k x 12 l = 196KB) lives
// in smem, so A is read from gmem ONCE (both passes hit smem).
#define NQUAD  32
#define SPQ    16                 // slices per quad
#define CH4    96                 // float4 per k-chunk row-plane output (32k x 3)
#define ROWB   1536               // bytes per j-row chunk (32k x 12l x 4B)
#define JT     8                  // j-rows per pipeline tile
#define NTILE  (Nn / JT)          // 16
#define TILEB  (JT * ROWB)        // 12288
#define CONS   384                // consumer threads (12 warps, 4 j-groups x 96)
#define THREADS (CONS + 32)       // + producer warp
#define SMEM_TOTAL (Nn * ROWB + 3 * NT4 * 16 + NTILE * 16)   // 215296

// Scratch: h = concat([x1, x2], channel axis) -> [B][2C][N*T] = 6.3 MB
__device__ float g_h[(size_t)Bn * 2 * Cn * NT];
// quad exchange flags; zeroed by a captured memset before every prop launch
__device__ unsigned long long g_flag[NQUAD][4];

__device__ __forceinline__ void fma4(float4& acc, const float4 a, const float4 v) {
    acc.x = fmaf(a.x, v.x, acc.x);
    acc.y = fmaf(a.y, v.y, acc.y);
    acc.z = fmaf(a.z, v.z, acc.z);
    acc.w = fmaf(a.w, v.w, acc.w);
}
__device__ __forceinline__ float4 add4(const float4 a, const float4 b) {
    return make_float4(a.x + b.x, a.y + b.y, a.z + b.z, a.w + b.w);
}

__device__ __forceinline__ uint32_t smem_u32(const void* p) {
    uint32_t a;
    asm("{ .reg .u64 t; cvta.to.shared.u64 t, %1; cvt.u32.u64 %0, t; }" : "=r"(a) : "l"(p));
    return a;
}

#define MBAR_INIT(addr, cnt) \
    asm volatile("mbarrier.init.shared.b64 [%0], %1;" :: "r"(addr), "r"(cnt) : "memory")
#define MBAR_EXPECT_TX(addr, bytes) \
    asm volatile("mbarrier.arrive.expect_tx.shared.b64 _, [%0], %1;" :: "r"(addr), "r"(bytes) : "memory")
#define MBAR_ARRIVE(addr) \
    asm volatile("mbarrier.arrive.shared.b64 _, [%0];" :: "r"(addr) : "memory")

#define MBAR_WAIT_PARITY(mbar, ph) do {                                        \
    uint32_t _m = (mbar), _p = (uint32_t)(ph), _done;                          \
    asm volatile("{\n\t.reg .pred p;\n\t"                                      \
        "mbarrier.try_wait.parity.acquire.cta.shared::cta.b64 p, [%1], %2;\n\t"\
        "selp.b32 %0, 1, 0, p;\n\t}"                                           \
        : "=r"(_done) : "r"(_m), "r"(_p) : "memory");                          \
    if (!_done) {                                                              \
        asm volatile("{\n\t.reg .pred P1;\n\t"                                 \
            "WL_%=:\n\t"                                                       \
            "mbarrier.try_wait.parity.acquire.cta.shared::cta.b64 P1, [%0], %1, 0x989680;\n\t" \
            "@P1 bra.uni WD_%=;\n\t"                                           \
            "bra.uni WL_%=;\n\t"                                               \
            "WD_%=:\n\t}"                                                      \
            :: "r"(_m), "r"(_p) : "memory");                                   \
    }                                                                          \
} while (0)

__device__ __forceinline__ void bulk_g2s(uint32_t dst, const void* src,
                                         uint32_t bytes, uint32_t mbar) {
    asm volatile(
        "cp.async.bulk.shared::cta.global.mbarrier::complete_tx::bytes [%0], [%1], %2, [%3];"
        :: "r"(dst), "l"(src), "r"(bytes), "r"(mbar) : "memory");
}

__device__ __forceinline__ unsigned long long ld_vol(const unsigned long long* p) {
    unsigned long long v;
    asm volatile("ld.volatile.global.u64 %0, [%1];" : "=l"(v) : "l"(p));
    return v;
}

// ---------------------------------------------------------------------------
// Kernel 1: fused propagation, single gmem read of A.
// smem holds the full k-chunk (16 tiles x 12KB) as a slice-granularity ring:
// tile t of slice it+1 refills as soon as pass-2(it) has read tile t.
// 384 consumers = 4 j-groups x 96 outputs; group g owns tiles 4g..4g+3
// (j in [32g, 32g+32)) for BOTH passes; partial sums reduced via smem.
// x1 chunks exchanged across the 4 quad CTAs through g_h (= h row) + flags.
// ---------------------------------------------------------------------------
__global__ __launch_bounds__(THREADS, 1)
void prop_kernel(const float* __restrict__ x, const float* __restrict__ A) {
    extern __shared__ char dsm[];
    float4*   As   = (float4*)dsm;              // 12288 f4 (196KB): [j][96]
    float4*   xs   = As + Nn * (ROWB / 16);     // 384: x slice [j*3+lq]
    float4*   x1f  = xs + NT4;                  // 384: full x1 [j*3+lq]
    float4*   part = x1f + NT4;                 // 384: 4 groups x 96
    uint64_t* mb   = (uint64_t*)(part + NT4);   // 16 x (full, empty)

    const int tid = threadIdx.x;
    const int q   = blockIdx.x >> 2;     // quad
    const int cq  = blockIdx.x & 3;      // k-chunk within quad
    const uint32_t mb0 = smem_u32(mb);   // full[t]=mb0+16t, empty[t]=+8

    if (tid == 0) {
#pragma unroll
        for (int tt = 0; tt < NTILE; ++tt) {
            MBAR_INIT(mb0 + 16 * tt, 1);       // full: one expect_tx arrive
            MBAR_INIT(mb0 + 16 * tt + 8, 3);   // empty: 3 warps of owning group
        }
    }
    __syncthreads();

    // ------------------------- Producer warp -------------------------
    if (tid >= CONS) {
        const int lane = tid - CONS;
        const uint32_t as0 = smem_u32(As);
#pragma unroll 1
        for (int it = 0; it < SPQ; ++it) {
            const int s = q * SPQ + it;
            const float* src0 = A + (size_t)s * Nn * NT + cq * (ROWB / 4);
            const int pparity = (it + 1) & 1;
#pragma unroll 1
            for (int tt = 0; tt < NTILE; ++tt) {
                MBAR_WAIT_PARITY(mb0 + 16 * tt + 8, pparity);
                __syncwarp();
                if (lane == 0) MBAR_EXPECT_TX(mb0 + 16 * tt, TILEB);
                __syncwarp();
                if (lane < JT) {
                    const int jr = tt * JT + lane;
                    bulk_g2s(as0 + (uint32_t)jr * ROWB,
                             src0 + (size_t)jr * NT, ROWB, mb0 + 16 * tt);
                }
            }
        }
        return;
    }

    // ------------------------- Consumers (384) -------------------------
    const int g  = tid / 96;      // j-group, owns tiles 4g..4g+3
    const int o  = tid % 96;      // output float4 within chunk
    const int lq = o % 3;
    const bool elect = ((tid & 31) == 0);

#pragma unroll 1
    for (int it = 0; it < SPQ; ++it) {
        const int s = q * SPQ + it;
        const int b = s / Cn;
        const int i = s % Cn;
        float4* hrow1 = (float4*)(g_h + ((size_t)b * 2 * Cn + i) * NT);
        const int fparity = it & 1;

        xs[tid] = ((const float4*)x)[(size_t)s * NT4 + tid];
        asm volatile("bar.sync 1, %0;" :: "r"(CONS) : "memory");

        // ---- Pass 1: partial x1_chunk over j in [32g, 32g+32)
        float4 acc = make_float4(0.f, 0.f, 0.f, 0.f);
#pragma unroll
        for (int tt2 = 0; tt2 < 4; ++tt2) {
            const int tt = 4 * g + tt2;
            MBAR_WAIT_PARITY(mb0 + 16 * tt, fparity);
            const float4* ap = As + (size_t)(tt * JT) * CH4;
            const float4* xp = xs + (tt * JT) * 3 + lq;
#pragma unroll
            for (int jj = 0; jj < JT; ++jj)
                fma4(acc, ap[jj * CH4 + o], xp[jj * 3]);
        }
        part[g * 96 + o] = acc;
        asm volatile("bar.sync 1, %0;" :: "r"(CONS) : "memory");

        // ---- Reduce + publish x1 chunk (g_h row IS h's x1 half)
        if (tid < 96) {
            float4 r1 = add4(add4(part[tid], part[96 + tid]),
                             add4(part[192 + tid], part[288 + tid]));
            x1f[cq * 96 + tid]  = r1;
            hrow1[cq * 96 + tid] = r1;
            __threadfence();
        }
        asm volatile("bar.sync 1, %0;" :: "r"(CONS) : "memory");
        if (tid == 0) {
            atomicAdd(&g_flag[q][cq], 1ULL);
            const unsigned long long tgt = (unsigned long long)(it + 1);
#pragma unroll
            for (int c = 0; c < 4; ++c)
                if (c != cq) while (ld_vol(&g_flag[q][c]) < tgt) { }
            __threadfence();
        }
        asm volatile("bar.sync 1, %0;" :: "r"(CONS) : "memory");
        if (tid < 288) {
            const int ci = tid / 96;
            const int c  = ci + (ci >= cq ? 1 : 0);
            const int p  = c * 96 + tid % 96;
            x1f[p] = hrow1[p];
        }
        asm volatile("bar.sync 1, %0;" :: "r"(CONS) : "memory");

        // ---- Pass 2: same A tiles from smem; free each tile after reading
        acc = make_float4(0.f, 0.f, 0.f, 0.f);
#pragma unroll
        for (int tt2 = 0; tt2 < 4; ++tt2) {
            const int tt = 4 * g + tt2;
            const float4* ap = As + (size_t)(tt * JT) * CH4;
            const float4* xp = x1f + (tt * JT) * 3 + lq;
#pragma unroll
            for (int jj = 0; jj < JT; ++jj)
                fma4(acc, ap[jj * CH4 + o], xp[jj * 3]);
            if (elect) MBAR_ARRIVE(mb0 + 16 * tt + 8);
        }
        part[g * 96 + o] = acc;
        asm volatile("bar.sync 1, %0;" :: "r"(CONS) : "memory");

        if (tid < 96) {
            float4 r2 = add4(add4(part[tid], part[96 + tid]),
                             add4(part[192 + tid], part[288 + tid]));
            ((float4*)(g_h + ((size_t)b * 2 * Cn + Cn + i) * NT))[cq * 96 + tid] = r2;
        }
    }
}

// ---------------------------------------------------------------------------
// Kernel 2: 1x1 conv channel mix, smem-tiled GEMM (proven R3 version).
// ---------------------------------------------------------------------------
#define MIX_COLS 64
#define MIX_NCB  (NT / MIX_COLS)   // 24

__global__ __launch_bounds__(256) void mix_kernel(const float* __restrict__ W,
                                                  const float* __restrict__ bias,
                                                  float* __restrict__ out) {
    __shared__ float4 hs[(2 * Cn) * (MIX_COLS / 4)];   // 16 KB
    __shared__ float  Ws[COn * 2 * Cn];                // 16 KB
    __shared__ float  bs[COn];

    const int t    = threadIdx.x;
    const int b    = blockIdx.x / MIX_NCB;
    const int col0 = (blockIdx.x % MIX_NCB) * MIX_COLS;
    const int colq = t & 15;
    const int oq   = t >> 4;

    {
        float4*       Wd = (float4*)Ws;
        const float4* W4 = (const float4*)W;
#pragma unroll
        for (int s = 0; s < 4; ++s) Wd[t + 256 * s] = W4[t + 256 * s];
        if (t < COn) bs[t] = bias[t];
    }
    {
        const float* hb = g_h + (size_t)b * 2 * Cn * NT + col0;
#pragma unroll
        for (int s = 0; s < 4; ++s) {
            int idx = t + 256 * s;
            int c   = idx >> 4;
            int v   = idx & 15;
            hs[idx] = ((const float4*)(hb + (size_t)c * NT))[v];
        }
    }
    __syncthreads();

    float4 acc0 = make_float4(bs[4 * oq + 0], bs[4 * oq + 0], bs[4 * oq + 0], bs[4 * oq + 0]);
    float4 acc1 = make_float4(bs[4 * oq + 1], bs[4 * oq + 1], bs[4 * oq + 1], bs[4 * oq + 1]);
    float4 acc2 = make_float4(bs[4 * oq + 2], bs[4 * oq + 2], bs[4 * oq + 2], bs[4 * oq + 2]);
    float4 acc3 = make_float4(bs[4 * oq + 3], bs[4 * oq + 3], bs[4 * oq + 3], bs[4 * oq + 3]);

#pragma unroll 8
    for (int c = 0; c < 2 * Cn; ++c) {
        float4 hv = hs[c * 16 + colq];
        float  w0 = Ws[(4 * oq + 0) * 2 * Cn + c];
        float  w1 = Ws[(4 * oq + 1) * 2 * Cn + c];
        float  w2 = Ws[(4 * oq + 2) * 2 * Cn + c];
        float  w3 = Ws[(4 * oq + 3) * 2 * Cn + c];
        acc0.x = fmaf(w0, hv.x, acc0.x); acc0.y = fmaf(w0, hv.y, acc0.y);
        acc0.z = fmaf(w0, hv.z, acc0.z); acc0.w = fmaf(w0, hv.w, acc0.w);
        acc1.x = fmaf(w1, hv.x, acc1.x); acc1.y = fmaf(w1, hv.y, acc1.y);
        acc1.z = fmaf(w1, hv.z, acc1.z); acc1.w = fmaf(w1, hv.w, acc1.w);
        acc2.x = fmaf(w2, hv.x, acc2.x); acc2.y = fmaf(w2, hv.y, acc2.y);
        acc2.z = fmaf(w2, hv.z, acc2.z); acc2.w = fmaf(w2, hv.w, acc2.w);
        acc3.x = fmaf(w3, hv.x, acc3.x); acc3.y = fmaf(w3, hv.y, acc3.y);
        acc3.z = fmaf(w3, hv.z, acc3.z); acc3.w = fmaf(w3, hv.w, acc3.w);
    }

    float* ob = out + (size_t)b * COn * NT + col0;
    ((float4*)(ob + (size_t)(4 * oq + 0) * NT))[colq] = acc0;
    ((float4*)(ob + (size_t)(4 * oq + 1) * NT))[colq] = acc1;
    ((float4*)(ob + (size_t)(4 * oq + 2) * NT))[colq] = acc2;
    ((float4*)(ob + (size_t)(4 * oq + 3) * NT))[colq] = acc3;
}

// ---------------------------------------------------------------------------
extern "C" void kernel_launch(void* const* d_in, const int* in_sizes, int n_in,
                              void* d_out, int out_size) {
    const float* x    = (const float*)d_in[0];   // [B,C,N,T]
    const float* A    = (const float*)d_in[1];   // [B,C,N,N,T]
    const float* W    = (const float*)d_in[2];   // [C_OUT, 2C]
    const float* bias = (const float*)d_in[3];   // [C_OUT]
    float* out = (float*)d_out;                  // [B,C_OUT,N,T]

    // zero the exchange flags every replay (memset node, graph-capturable)
    void* fp = nullptr;
    cudaGetSymbolAddress(&fp, g_flag);
    cudaMemsetAsync(fp, 0, sizeof(unsigned long long) * NQUAD * 4);

    cudaFuncSetAttribute(prop_kernel, cudaFuncAttributeMaxDynamicSharedMemorySize,
                         SMEM_TOTAL);

    prop_kernel<<<4 * NQUAD, THREADS, SMEM_TOTAL>>>(x, A);
    mix_kernel<<<Bn * MIX_NCB, 256>>>(W, bias, out);
}

// round 10
// speedup vs baseline: 1.2723x; 1.2723x over previous
#include <cuda_runtime.h>

// Problem constants
#define Bn  16
#define Cn  32
#define Nn  128
#define Tn  12
#define COn 64
#define NT  (Nn * Tn)          // 1536 floats per (b,i,j) row of A
#define NT4 (NT / 4)           // 384 float4
#define NSLICE (Bn * Cn)       // 512 (b,i) slices

// prop config: 128 persistent CTAs (1/SM via smem pad), 768 threads =
// 4 groups x 192; each group streams 32 of the 128 j-rows.
#define PROP_CTAS    128
#define PROP_THREADS 768
#define NGRP 4
#define GSZ  192
#define JPG  (Nn / NGRP)       // 32
#define PROP_PAD (150 * 1024)  // dummy dynamic smem -> 1 CTA/SM

// Anti-phase stagger: odd CTAs delay ~8us so their pass-1 (HBM) overlaps
// even CTAs' pass-2 (L2), keeping both HBM and LTS busy continuously.
#define STAGGER_CYCLES 16000LL

// Scratch: h = concat([x1, x2], channel axis) -> [B][2C][N*T] = 6.3 MB
__device__ float g_h[(size_t)Bn * 2 * Cn * NT];

extern __shared__ char s_pad[];   // occupancy limiter (never accessed)

__device__ __forceinline__ void fma4(float4& acc, const float4 a, const float4 v) {
    acc.x = fmaf(a.x, v.x, acc.x);
    acc.y = fmaf(a.y, v.y, acc.y);
    acc.z = fmaf(a.z, v.z, acc.z);
    acc.w = fmaf(a.w, v.w, acc.w);
}
__device__ __forceinline__ float4 add4(const float4 a, const float4 b) {
    return make_float4(a.x + b.x, a.y + b.y, a.z + b.z, a.w + b.w);
}

// ---------------------------------------------------------------------------
// Kernel 1: fused order-1 + order-2 propagation (R3 structure, proven 92us)
// + anti-phase stagger. Persistent, 1 CTA/SM, 24 warps. Pass 1 streams the
// slice from HBM (fills L2); pass 2 re-reads it from L2. Odd CTAs start
// ~8us late so chip-wide the two phases interleave across CTA parity:
// HBM (fills) and LTS (L2 reads) stay concurrently busy, while each SM
// still issues a single-latency-class load stream at any moment.
// Concurrent L2 footprint stays ~128 x 786KB = 100MB <= 126MB.
// ---------------------------------------------------------------------------
__global__ __launch_bounds__(PROP_THREADS, 1)
void prop_kernel(const float* __restrict__ x, const float* __restrict__ A) {
    __shared__ float4 part[NGRP][NT4];   // 24 KB partial sums
    __shared__ float4 xs[NT4];           // x slice,  [j*3 + lq]
    __shared__ float4 x1s[NT4];          // x1 slice, same layout

    const int t  = threadIdx.x;
    const int g  = t / GSZ;
    const int ti = t - g * GSZ;          // 0..191
    const int lq = ti % 3;
    const int j0 = g * JPG;

    // one-shot anti-phase delay for odd CTAs
    if (blockIdx.x & 1) {
        const long long start = clock64();
        while (clock64() - start < STAGGER_CYCLES) { }
    }

    for (int bc = blockIdx.x; bc < NSLICE; bc += PROP_CTAS) {
        const float4* __restrict__ xp = (const float4*)(x + (size_t)bc * NT);
        const float4* __restrict__ Ap = (const float4*)(A + (size_t)bc * Nn * NT);

        if (t < NT4) xs[t] = xp[t];
        __syncthreads();   // also the end-of-previous-iteration barrier

        // ---- Pass 1: x1[k,l] = sum_j x[j,l] * A[j,k,l]  (HBM stream)
        float4 acc0 = make_float4(0.f, 0.f, 0.f, 0.f);
        float4 acc1 = make_float4(0.f, 0.f, 0.f, 0.f);
        {
            const float4* __restrict__ ap = Ap + (size_t)j0 * NT4;
#pragma unroll 8
            for (int jj = 0; jj < JPG; ++jj) {
                float4 a0 = ap[jj * NT4 + ti];
                float4 a1 = ap[jj * NT4 + ti + GSZ];
                float4 xv = xs[(j0 + jj) * 3 + lq];
                fma4(acc0, a0, xv);
                fma4(acc1, a1, xv);
            }
        }
        part[g][ti]       = acc0;
        part[g][ti + GSZ] = acc1;
        __syncthreads();

        // ---- Reduce 1: x1 = sum of 4 partials
        float4 r1;
        if (t < NT4) {
            r1 = add4(add4(part[0][t], part[1][t]), add4(part[2][t], part[3][t]));
            x1s[t] = r1;
        }
        __syncthreads();

        // ---- Pass 2: x2[k,l] = sum_j x1[j,l] * A[j,k,l]  (L2 re-read)
        acc0 = make_float4(0.f, 0.f, 0.f, 0.f);
        acc1 = make_float4(0.f, 0.f, 0.f, 0.f);
        {
            const float4* __restrict__ ap = Ap + (size_t)j0 * NT4;
#pragma unroll 8
            for (int jj = 0; jj < JPG; ++jj) {
                float4 a0 = __ldlu(&ap[jj * NT4 + ti]);
                float4 a1 = __ldlu(&ap[jj * NT4 + ti + GSZ]);
                float4 xv = x1s[(j0 + jj) * 3 + lq];
                fma4(acc0, a0, xv);
                fma4(acc1, a1, xv);
            }
        }
        part[g][ti]       = acc0;
        part[g][ti + GSZ] = acc1;
        __syncthreads();

        // ---- Reduce 2 + write h[b,i,:] = x1, h[b,C+i,:] = x2
        if (t < NT4) {
            float4 r2 = add4(add4(part[0][t], part[1][t]), add4(part[2][t], part[3][t]));
            const int b = bc / Cn;
            const int i = bc % Cn;
            ((float4*)(g_h + ((size_t)b * 2 * Cn + i) * NT))[t]      = r1;
            ((float4*)(g_h + ((size_t)b * 2 * Cn + Cn + i) * NT))[t] = r2;
        }
    }
}

// ---------------------------------------------------------------------------
// Kernel 2: 1x1 conv channel mix, smem-tiled GEMM (exact R3 version, 10.6us).
// ---------------------------------------------------------------------------
#define MIX_COLS 64
#define MIX_NCB  (NT / MIX_COLS)   // 24

__global__ __launch_bounds__(256) void mix_kernel(const float* __restrict__ W,
                                                  const float* __restrict__ bias,
                                                  float* __restrict__ out) {
    __shared__ float4 hs[(2 * Cn) * (MIX_COLS / 4)];   // 16 KB
    __shared__ float  Ws[COn * 2 * Cn];                // 16 KB
    __shared__ float  bs[COn];

    const int t    = threadIdx.x;
    const int b    = blockIdx.x / MIX_NCB;
    const int col0 = (blockIdx.x % MIX_NCB) * MIX_COLS;
    const int colq = t & 15;
    const int oq   = t >> 4;

    {
        float4*       Wd = (float4*)Ws;
        const float4* W4 = (const float4*)W;
#pragma unroll
        for (int s = 0; s < 4; ++s) Wd[t + 256 * s] = W4[t + 256 * s];
        if (t < COn) bs[t] = bias[t];
    }
    {
        const float* hb = g_h + (size_t)b * 2 * Cn * NT + col0;
#pragma unroll
        for (int s = 0; s < 4; ++s) {
            int idx = t + 256 * s;
            int c   = idx >> 4;
            int v   = idx & 15;
            hs[idx] = ((const float4*)(hb + (size_t)c * NT))[v];
        }
    }
    __syncthreads();

    float4 acc0 = make_float4(bs[4 * oq + 0], bs[4 * oq + 0], bs[4 * oq + 0], bs[4 * oq + 0]);
    float4 acc1 = make_float4(bs[4 * oq + 1], bs[4 * oq + 1], bs[4 * oq + 1], bs[4 * oq + 1]);
    float4 acc2 = make_float4(bs[4 * oq + 2], bs[4 * oq + 2], bs[4 * oq + 2], bs[4 * oq + 2]);
    float4 acc3 = make_float4(bs[4 * oq + 3], bs[4 * oq + 3], bs[4 * oq + 3], bs[4 * oq + 3]);

#pragma unroll 8
    for (int c = 0; c < 2 * Cn; ++c) {
        float4 hv = hs[c * 16 + colq];
        float  w0 = Ws[(4 * oq + 0) * 2 * Cn + c];
        float  w1 = Ws[(4 * oq + 1) * 2 * Cn + c];
        float  w2 = Ws[(4 * oq + 2) * 2 * Cn + c];
        float  w3 = Ws[(4 * oq + 3) * 2 * Cn + c];
        acc0.x = fmaf(w0, hv.x, acc0.x); acc0.y = fmaf(w0, hv.y, acc0.y);
        acc0.z = fmaf(w0, hv.z, acc0.z); acc0.w = fmaf(w0, hv.w, acc0.w);
        acc1.x = fmaf(w1, hv.x, acc1.x); acc1.y = fmaf(w1, hv.y, acc1.y);
        acc1.z = fmaf(w1, hv.z, acc1.z); acc1.w = fmaf(w1, hv.w, acc1.w);
        acc2.x = fmaf(w2, hv.x, acc2.x); acc2.y = fmaf(w2, hv.y, acc2.y);
        acc2.z = fmaf(w2, hv.z, acc2.z); acc2.w = fmaf(w2, hv.w, acc2.w);
        acc3.x = fmaf(w3, hv.x, acc3.x); acc3.y = fmaf(w3, hv.y, acc3.y);
        acc3.w = fmaf(w3, hv.w, acc3.w); acc3.z = fmaf(w3, hv.z, acc3.z);
    }

    float* ob = out + (size_t)b * COn * NT + col0;
    ((float4*)(ob + (size_t)(4 * oq + 0) * NT))[colq] = acc0;
    ((float4*)(ob + (size_t)(4 * oq + 1) * NT))[colq] = acc1;
    ((float4*)(ob + (size_t)(4 * oq + 2) * NT))[colq] = acc2;
    ((float4*)(ob + (size_t)(4 * oq + 3) * NT))[colq] = acc3;
}

// ---------------------------------------------------------------------------
extern "C" void kernel_launch(void* const* d_in, const int* in_sizes, int n_in,
                              void* d_out, int out_size) {
    const float* x    = (const float*)d_in[0];   // [B,C,N,T]
    const float* A    = (const float*)d_in[1];   // [B,C,N,N,T]
    const float* W    = (const float*)d_in[2];   // [C_OUT, 2C]
    const float* bias = (const float*)d_in[3];   // [C_OUT]
    float* out = (float*)d_out;                  // [B,C_OUT,N,T]

    cudaFuncSetAttribute(prop_kernel, cudaFuncAttributeMaxDynamicSharedMemorySize, PROP_PAD);

    prop_kernel<<<PROP_CTAS, PROP_THREADS, PROP_PAD>>>(x, A);
    mix_kernel<<<Bn * MIX_NCB, 256>>>(W, bias, out);
}